// round 9
// baseline (speedup 1.0000x reference)
#include <cuda_runtime.h>
#include <cuda_bf16.h>
#include <stdint.h>

#define F 128
#define NMAX 100000
#define EMAX 1700000   // E + N self loops
#define NTILES 6256    // ceil(100096/16): padded so every GEMM tile is in-bounds

// ---------------- scratch (alloc-free: __device__ globals) ----------------
__device__ float g_h[NMAX * F];                 // transformed features h = feat @ W
// layer input in mma-A fragment layout: tile t (16 rows) x k-chunk kc (16 cols)
// -> 32 lanes x 4 regs (uint4 per lane). index: ((t*8+kc)*32 + lane) uint4s.
__device__ uint32_t g_xhf[NTILES * 1024];       // bf16 hi pairs
__device__ uint32_t g_xlf[NTILES * 1024];       // bf16 lo pairs
__device__ __nv_bfloat16 g_wh[3][F * F];        // W bf16 hi per layer
__device__ __nv_bfloat16 g_wl[3][F * F];        // W bf16 lo per layer
__device__ float g_asrc[NMAX];
__device__ float g_adst[NMAX];
__device__ int   g_deg[NMAX];
__device__ int   g_rowptr[NMAX + 1];
__device__ int   g_cursor[NMAX];
__device__ int   g_srcs[EMAX];                  // src indices sorted by dst (CSR)
__device__ int   g_bsum[256];                   // scan block sums
__device__ int   g_bpre[257];                   // scan block prefixes (+ total)

// ---------------- helpers ----------------
__device__ __forceinline__ uint32_t smem_u32(const void* p) {
    uint32_t a;
    asm("{ .reg .u64 t; cvta.to.shared.u64 t, %1; cvt.u32.u64 %0, t; }" : "=r"(a) : "l"(p));
    return a;
}
__device__ __forceinline__ void ldsm_x4_t(uint32_t* r, uint32_t addr) {
    asm volatile("ldmatrix.sync.aligned.m8n8.x4.trans.shared.b16 {%0,%1,%2,%3}, [%4];"
                 : "=r"(r[0]), "=r"(r[1]), "=r"(r[2]), "=r"(r[3]) : "r"(addr));
}
__device__ __forceinline__ void mma_bf16(float* c, const uint32_t* a, const uint32_t* b) {
    asm volatile("mma.sync.aligned.m16n8k16.row.col.f32.bf16.bf16.f32 "
                 "{%0,%1,%2,%3}, {%4,%5,%6,%7}, {%8,%9}, {%0,%1,%2,%3};"
                 : "+f"(c[0]), "+f"(c[1]), "+f"(c[2]), "+f"(c[3])
                 : "r"(a[0]), "r"(a[1]), "r"(a[2]), "r"(a[3]), "r"(b[0]), "r"(b[1]));
}
__device__ __forceinline__ void split_bf16(float x, __nv_bfloat16& h, __nv_bfloat16& l) {
    h = __float2bfloat16_rn(x);
    l = __float2bfloat16_rn(x - __bfloat162float(h));
}
// split 4 consecutive cols (c4 aligned to 4) of one row into fragment-layout stores
__device__ __forceinline__ void split4_frag_store(float4 v, int row, int c4) {
    __nv_bfloat16 h0, l0, h1, l1, h2, l2, h3, l3;
    split_bf16(v.x, h0, l0); split_bf16(v.y, h1, l1);
    split_bf16(v.z, h2, l2); split_bf16(v.w, h3, l3);
    uint32_t hx = (uint32_t)__bfloat16_as_ushort(h0) | ((uint32_t)__bfloat16_as_ushort(h1) << 16);
    uint32_t hy = (uint32_t)__bfloat16_as_ushort(h2) | ((uint32_t)__bfloat16_as_ushort(h3) << 16);
    uint32_t lx = (uint32_t)__bfloat16_as_ushort(l0) | ((uint32_t)__bfloat16_as_ushort(l1) << 16);
    uint32_t ly = (uint32_t)__bfloat16_as_ushort(l2) | ((uint32_t)__bfloat16_as_ushort(l3) << 16);
    int t = row >> 4, rr = row & 15, kc = c4 >> 4, cc0 = c4 & 15;
    uint32_t base = (uint32_t)(((t * 8 + kc) * 32 + (rr & 7) * 4 + ((cc0 & 7) >> 1)) * 4
                               + (rr >> 3) + (((cc0 >> 3) & 1) << 1));
    g_xhf[base] = hx; g_xhf[base + 4] = hy;
    g_xlf[base] = lx; g_xlf[base + 4] = ly;
}

// ---------------- input / weight splitting ----------------
__global__ void k_split_x(const float* __restrict__ x, int total4) {
    int i = blockIdx.x * blockDim.x + threadIdx.x;
    if (i >= total4) return;
    float4 v = ((const float4*)x)[i];
    split4_frag_store(v, i >> 5, (i & 31) * 4);
}
__global__ void k_prepW_all(const float* __restrict__ W0, const float* __restrict__ W1,
                            const float* __restrict__ W2) {
    int i = blockIdx.x * blockDim.x + threadIdx.x;
    if (i >= 3 * 4096) return;
    int l = i >> 12, j = i & 4095;
    const float* W = (l == 0) ? W0 : (l == 1) ? W1 : W2;
    float4 v = ((const float4*)W)[j];
    __nv_bfloat16 h0, l0, h1, l1, h2, l2, h3, l3;
    split_bf16(v.x, h0, l0); split_bf16(v.y, h1, l1);
    split_bf16(v.z, h2, l2); split_bf16(v.w, h3, l3);
    g_wh[l][j * 4 + 0] = h0; g_wh[l][j * 4 + 1] = h1;
    g_wh[l][j * 4 + 2] = h2; g_wh[l][j * 4 + 3] = h3;
    g_wl[l][j * 4 + 0] = l0; g_wl[l][j * 4 + 1] = l1;
    g_wl[l][j * 4 + 2] = l2; g_wl[l][j * 4 + 3] = l3;
}

// ---------------- CSR build ----------------
__global__ void k_zero_deg(int N) {
    int i = blockIdx.x * blockDim.x + threadIdx.x;
    if (i < N) g_deg[i] = 0;
}
__global__ void k_count(const int* __restrict__ ei, int E, int N) {
    int j = blockIdx.x * blockDim.x + threadIdx.x;
    if (j >= E + N) return;
    int d = (j < E) ? ei[E + j] : (j - E);
    atomicAdd(&g_deg[d], 1);
}
__global__ void k_scan1(int N) {
    __shared__ int s[256];
    int t = threadIdx.x, b = blockIdx.x;
    int i0 = b * 1024 + t * 4;
    int sum = 0;
#pragma unroll
    for (int j = 0; j < 4; j++)
        if (i0 + j < N) sum += g_deg[i0 + j];
    s[t] = sum;
    __syncthreads();
#pragma unroll
    for (int off = 128; off; off >>= 1) {
        if (t < off) s[t] += s[t + off];
        __syncthreads();
    }
    if (t == 0) g_bsum[b] = s[0];
}
__global__ void k_scan2(int nb) {
    __shared__ int s[256];
    int t = threadIdx.x;
    int v = (t < nb) ? g_bsum[t] : 0;
    s[t] = v;
    __syncthreads();
#pragma unroll
    for (int off = 1; off < 256; off <<= 1) {
        int u = (t >= off) ? s[t - off] : 0;
        __syncthreads();
        s[t] += u;
        __syncthreads();
    }
    if (t <= nb) g_bpre[t] = (t == 0) ? 0 : s[t - 1];
    if (t == 255) g_bpre[256] = s[255];
}
__global__ void k_scan3(int N, int nb) {
    __shared__ int s[256];
    int t = threadIdx.x, b = blockIdx.x;
    int i0 = b * 1024 + t * 4;
    int d[4];
    int sum = 0;
#pragma unroll
    for (int j = 0; j < 4; j++) {
        d[j] = (i0 + j < N) ? g_deg[i0 + j] : 0;
        sum += d[j];
    }
    s[t] = sum;
    __syncthreads();
#pragma unroll
    for (int off = 1; off < 256; off <<= 1) {
        int u = (t >= off) ? s[t - off] : 0;
        __syncthreads();
        s[t] += u;
        __syncthreads();
    }
    int run = g_bpre[b] + s[t] - sum;
#pragma unroll
    for (int j = 0; j < 4; j++) {
        if (i0 + j < N) {
            g_rowptr[i0 + j] = run;
            g_cursor[i0 + j] = run;
        }
        run += d[j];
    }
    if (b == 0 && t == 0) g_rowptr[N] = g_bpre[nb];
}
__global__ void k_scatter(const int* __restrict__ ei, int E, int N) {
    int j = blockIdx.x * blockDim.x + threadIdx.x;
    if (j >= E + N) return;
    int sIdx, d;
    if (j < E) { sIdx = ei[j]; d = ei[E + j]; }
    else       { sIdx = j - E; d = j - E; }
    int pos = atomicAdd(&g_cursor[d], 1);
    g_srcs[pos] = sIdx;
}

// ---------------- bf16x3 tensor-core GEMM: A frags direct from global ----------------
// 512 threads, 16 warps 4(M)x4(N), warp tile 32x32. A: LDG.128 fragments (no smem).
// B: hi/lo smem images + ldsm_t. smem ~72KB.
#define AS_STRIDE 136
#define B_TILE_B (128 * AS_STRIDE * 2)   // 34816
#define OFF_BH 0
#define OFF_BL (B_TILE_B)
#define OFF_SAS (2 * B_TILE_B)
#define OFF_SAD (OFF_SAS + 512)
#define OFF_SUA (OFF_SAD + 512)
#define OFF_SUD (OFF_SUA + 512)
#define GEMM_SMEM (OFF_SUD + 512)

__global__ void __launch_bounds__(512)
k_gemm_mma(int layer, const float* __restrict__ av_s, const float* __restrict__ av_d, int Nn) {
    extern __shared__ char smem[];
    const uint32_t sb = smem_u32(smem);
    const int tid = threadIdx.x, lane = tid & 31, wid = tid >> 5;
    const int row0 = blockIdx.x * 128;

    float* s_as = (float*)(smem + OFF_SAS);
    float* s_ad = (float*)(smem + OFF_SAD);
    float* s_ua = (float*)(smem + OFF_SUA);
    float* s_ud = (float*)(smem + OFF_SUD);
    if (tid < 128) {
        s_as[tid] = av_s[tid];
        s_ad[tid] = av_d[tid];
        s_ua[tid] = 0.f;
        s_ud[tid] = 0.f;
    }

    {   // stage B: 128 rows, 4 threads/row, 32 elems (4x uint4) per image
        int r = tid >> 2, seg = (tid & 3) * 32;
        const uint4* sBh = (const uint4*)&g_wh[layer][r * 128 + seg];
        const uint4* sBl = (const uint4*)&g_wl[layer][r * 128 + seg];
        uint4* dBh = (uint4*)((__nv_bfloat16*)(smem + OFF_BH) + r * AS_STRIDE + seg);
        uint4* dBl = (uint4*)((__nv_bfloat16*)(smem + OFF_BL) + r * AS_STRIDE + seg);
#pragma unroll
        for (int j = 0; j < 4; j++) {
            dBh[j] = sBh[j];
            dBl[j] = sBl[j];
        }
    }
    __syncthreads();

    const int wm = wid & 3, wn = wid >> 2;
    const int wrow = wm * 32, wcol = wn * 32;
    const int gt0 = blockIdx.x * 8 + wm * 2;     // this warp's two 16-row A tiles
    float acc[2][4][4];
#pragma unroll
    for (int i = 0; i < 2; i++)
#pragma unroll
        for (int j = 0; j < 4; j++)
#pragma unroll
            for (int q = 0; q < 4; q++) acc[i][j][q] = 0.f;

    const int lr = lane & 15, lc = lane >> 4;
#pragma unroll
    for (int pass = 0; pass < 3; pass++) {
        const uint4* __restrict__ Af = (const uint4*)((pass == 1) ? g_xlf : g_xhf);
        uint32_t boff = sb + ((pass == 2) ? OFF_BL : OFF_BH);
#pragma unroll
        for (int ks = 0; ks < 8; ks++) {
            uint4 f0 = __ldg(&Af[(size_t)(gt0 * 8 + ks) * 32 + lane]);
            uint4 f1 = __ldg(&Af[(size_t)((gt0 + 1) * 8 + ks) * 32 + lane]);
            uint32_t b[2][4];
#pragma unroll
            for (int ng = 0; ng < 2; ng++)
                ldsm_x4_t(b[ng], boff + ((ks * 16 + lr) * AS_STRIDE + wcol + ng * 16 + lc * 8) * 2);
            uint32_t a0[4] = {f0.x, f0.y, f0.z, f0.w};
            uint32_t a1[4] = {f1.x, f1.y, f1.z, f1.w};
#pragma unroll
            for (int nt = 0; nt < 4; nt++) {
                mma_bf16(acc[0][nt], a0, &b[nt >> 1][(nt & 1) * 2]);
                mma_bf16(acc[1][nt], a1, &b[nt >> 1][(nt & 1) * 2]);
            }
        }
    }

    float pa[4] = {0.f, 0.f, 0.f, 0.f}, pd[4] = {0.f, 0.f, 0.f, 0.f};
#pragma unroll
    for (int mt = 0; mt < 2; mt++) {
#pragma unroll
        for (int half = 0; half < 2; half++) {
            int rl = wrow + mt * 16 + half * 8 + (lane >> 2);
            int gr = row0 + rl;
            bool ok = gr < Nn;
#pragma unroll
            for (int nt = 0; nt < 4; nt++) {
                int cl = wcol + nt * 8 + (lane & 3) * 2;
                float v0 = acc[mt][nt][half * 2 + 0];
                float v1 = acc[mt][nt][half * 2 + 1];
                if (ok) *(float2*)&g_h[(size_t)gr * 128 + cl] = make_float2(v0, v1);
                pa[mt * 2 + half] += v0 * s_as[cl] + v1 * s_as[cl + 1];
                pd[mt * 2 + half] += v0 * s_ad[cl] + v1 * s_ad[cl + 1];
            }
        }
    }
#pragma unroll
    for (int i = 0; i < 4; i++) {
        int rl = wrow + (i >> 1) * 16 + (i & 1) * 8 + (lane >> 2);
        atomicAdd(&s_ua[rl], pa[i]);
        atomicAdd(&s_ud[rl], pd[i]);
    }
    __syncthreads();
    if (tid < 128 && row0 + tid < Nn) {
        g_asrc[row0 + tid] = s_ua[tid];
        g_adst[row0 + tid] = s_ud[tid];
    }
}

// ---------------- two-pass softmax aggregation, one warp per dst ----------------
__global__ void k_aggregate(const float* __restrict__ bias, float* __restrict__ outp,
                            int N, int write_final) {
    int warp = (blockIdx.x * blockDim.x + threadIdx.x) >> 5;
    int lane = threadIdx.x & 31;
    if (warp >= N) return;

    int beg = g_rowptr[warp];
    int end = g_rowptr[warp + 1];
    float ad = g_adst[warp];

    // pass 1: segment max
    float m = -1e30f;
    for (int e = beg + lane; e < end; e += 32) {
        int s = __ldg(&g_srcs[e]);
        float v = __ldg(&g_asrc[s]) + ad;
        v = v > 0.f ? v : 0.2f * v;
        m = fmaxf(m, v);
    }
#pragma unroll
    for (int off = 16; off; off >>= 1)
        m = fmaxf(m, __shfl_xor_sync(0xffffffffu, m, off));

    // pass 2: unnormalized weighted sum
    float4 acc = make_float4(0.f, 0.f, 0.f, 0.f);
    float denom = 0.f;
    for (int base = beg; base < end; base += 32) {
        int e = base + lane;
        float w = 0.f;
        int s = 0;
        if (e < end) {
            s = __ldg(&g_srcs[e]);
            float v = __ldg(&g_asrc[s]) + ad;
            v = v > 0.f ? v : 0.2f * v;
            w = __expf(v - m);
        }
        denom += w;
        int cnt = min(32, end - base);
        for (int i = 0; i < cnt; i++) {
            float wi = __shfl_sync(0xffffffffu, w, i);
            int   si = __shfl_sync(0xffffffffu, s, i);
            float4 hv = __ldg((const float4*)&g_h[(size_t)si * 128 + lane * 4]);
            acc.x += wi * hv.x; acc.y += wi * hv.y;
            acc.z += wi * hv.z; acc.w += wi * hv.w;
        }
    }
#pragma unroll
    for (int off = 16; off; off >>= 1)
        denom += __shfl_xor_sync(0xffffffffu, denom, off);

    float inv = 1.f / denom;
    float4 bv = *(const float4*)&bias[lane * 4];
    float4 r;
    r.x = acc.x * inv + bv.x;
    r.y = acc.y * inv + bv.y;
    r.z = acc.z * inv + bv.z;
    r.w = acc.w * inv + bv.w;
    if (write_final) {
        *(float4*)&outp[(size_t)warp * 128 + lane * 4] = r;
    } else {
        r.x = r.x > 0.f ? r.x : expm1f(r.x);
        r.y = r.y > 0.f ? r.y : expm1f(r.y);
        r.z = r.z > 0.f ? r.z : expm1f(r.z);
        r.w = r.w > 0.f ? r.w : expm1f(r.w);
        split4_frag_store(r, warp, lane * 4);
    }
}

// ---------------- launch ----------------
extern "C" void kernel_launch(void* const* d_in, const int* in_sizes, int n_in,
                              void* d_out, int out_size) {
    const float* x  = (const float*)d_in[0];
    const int*   ei = (const int*)d_in[1];
    int N  = in_sizes[0] / F;
    int E  = in_sizes[1] / 2;
    int ET = E + N;
    int nb = (N + 1023) / 1024;

    static int smem_set = 0;
    if (!smem_set) {
        cudaFuncSetAttribute(k_gemm_mma, cudaFuncAttributeMaxDynamicSharedMemorySize, GEMM_SMEM);
        smem_set = 1;
    }

    int warp_blocks = (N * 32 + 255) / 256;
    int gemm_blocks = (N + 127) / 128;

    // launch #4 = k_gemm_mma (ncu captures the 4th launch)
    k_split_x<<<(N * 32 + 255) / 256, 256>>>(x, N * 32);
    k_prepW_all<<<48, 256>>>((const float*)d_in[2], (const float*)d_in[6], (const float*)d_in[10]);
    k_zero_deg<<<(N + 255) / 256, 256>>>(N);
    k_gemm_mma<<<gemm_blocks, 512, GEMM_SMEM>>>(0, (const float*)d_in[3], (const float*)d_in[4], N);
    k_count<<<(ET + 255) / 256, 256>>>(ei, E, N);
    k_scan1<<<nb, 256>>>(N);
    k_scan2<<<1, 256>>>(nb);
    k_scan3<<<nb, 256>>>(N, nb);
    k_scatter<<<(ET + 255) / 256, 256>>>(ei, E, N);

    for (int l = 0; l < 3; l++) {
        const float* as = (const float*)d_in[3 + 4 * l];
        const float* ad = (const float*)d_in[4 + 4 * l];
        const float* b  = (const float*)d_in[5 + 4 * l];
        if (l > 0)
            k_gemm_mma<<<gemm_blocks, 512, GEMM_SMEM>>>(l, as, ad, N);
        k_aggregate<<<warp_blocks, 256>>>(b, l == 2 ? (float*)d_out : nullptr, N, l == 2 ? 1 : 0);
    }
}

// round 10
// speedup vs baseline: 1.2433x; 1.2433x over previous
#include <cuda_runtime.h>
#include <cuda_bf16.h>
#include <cuda_fp16.h>
#include <stdint.h>

#define F 128
#define NMAX 100000
#define EMAX 1700000   // E + N self loops

// ---------------- scratch (alloc-free: __device__ globals) ----------------
__device__ __half g_h[NMAX * F];                // transformed features h = feat @ W (fp16)
__device__ __nv_bfloat16 g_xh[NMAX * F];        // current layer input, bf16 hi
__device__ __nv_bfloat16 g_xl[NMAX * F];        // current layer input, bf16 lo
__device__ __nv_bfloat16 g_wh[3][F * F];        // W bf16 hi per layer
__device__ __nv_bfloat16 g_wl[3][F * F];        // W bf16 lo per layer
__device__ float g_asrc[NMAX];
__device__ float g_adst[NMAX];
__device__ int   g_deg[NMAX];
__device__ int   g_rowptr[NMAX + 1];
__device__ int   g_cursor[NMAX];
__device__ int   g_srcs[EMAX];                  // src indices sorted by dst (CSR)
__device__ int   g_bsum[256];                   // scan block sums
__device__ int   g_bpre[257];                   // scan block prefixes (+ total)

// ---------------- helpers ----------------
__device__ __forceinline__ uint32_t smem_u32(const void* p) {
    uint32_t a;
    asm("{ .reg .u64 t; cvta.to.shared.u64 t, %1; cvt.u32.u64 %0, t; }" : "=r"(a) : "l"(p));
    return a;
}
__device__ __forceinline__ void ldsm_x4(uint32_t* r, uint32_t addr) {
    asm volatile("ldmatrix.sync.aligned.m8n8.x4.shared.b16 {%0,%1,%2,%3}, [%4];"
                 : "=r"(r[0]), "=r"(r[1]), "=r"(r[2]), "=r"(r[3]) : "r"(addr));
}
__device__ __forceinline__ void ldsm_x4_t(uint32_t* r, uint32_t addr) {
    asm volatile("ldmatrix.sync.aligned.m8n8.x4.trans.shared.b16 {%0,%1,%2,%3}, [%4];"
                 : "=r"(r[0]), "=r"(r[1]), "=r"(r[2]), "=r"(r[3]) : "r"(addr));
}
__device__ __forceinline__ void mma_bf16(float* c, const uint32_t* a, const uint32_t* b) {
    asm volatile("mma.sync.aligned.m16n8k16.row.col.f32.bf16.bf16.f32 "
                 "{%0,%1,%2,%3}, {%4,%5,%6,%7}, {%8,%9}, {%0,%1,%2,%3};"
                 : "+f"(c[0]), "+f"(c[1]), "+f"(c[2]), "+f"(c[3])
                 : "r"(a[0]), "r"(a[1]), "r"(a[2]), "r"(a[3]), "r"(b[0]), "r"(b[1]));
}
__device__ __forceinline__ void split_bf16(float x, __nv_bfloat16& h, __nv_bfloat16& l) {
    h = __float2bfloat16_rn(x);
    l = __float2bfloat16_rn(x - __bfloat162float(h));
}
__device__ __forceinline__ void split4_store(float4 r, __nv_bfloat16* ph, __nv_bfloat16* pl) {
    __nv_bfloat16 h0, l0, h1, l1, h2, l2, h3, l3;
    split_bf16(r.x, h0, l0); split_bf16(r.y, h1, l1);
    split_bf16(r.z, h2, l2); split_bf16(r.w, h3, l3);
    uint2 hp, lp;
    hp.x = (uint32_t)__bfloat16_as_ushort(h0) | ((uint32_t)__bfloat16_as_ushort(h1) << 16);
    hp.y = (uint32_t)__bfloat16_as_ushort(h2) | ((uint32_t)__bfloat16_as_ushort(h3) << 16);
    lp.x = (uint32_t)__bfloat16_as_ushort(l0) | ((uint32_t)__bfloat16_as_ushort(l1) << 16);
    lp.y = (uint32_t)__bfloat16_as_ushort(l2) | ((uint32_t)__bfloat16_as_ushort(l3) << 16);
    *(uint2*)ph = hp;
    *(uint2*)pl = lp;
}

// ---------------- input / weight splitting ----------------
__global__ void k_split_x(const float* __restrict__ x, int total4) {
    int i = blockIdx.x * blockDim.x + threadIdx.x;
    if (i >= total4) return;
    float4 v = ((const float4*)x)[i];
    split4_store(v, &g_xh[i * 4], &g_xl[i * 4]);
}
__global__ void k_prepW_all(const float* __restrict__ W0, const float* __restrict__ W1,
                            const float* __restrict__ W2) {
    int i = blockIdx.x * blockDim.x + threadIdx.x;
    if (i >= 3 * 4096) return;
    int l = i >> 12, j = i & 4095;
    const float* W = (l == 0) ? W0 : (l == 1) ? W1 : W2;
    float4 v = ((const float4*)W)[j];
    split4_store(v, &g_wh[l][j * 4], &g_wl[l][j * 4]);
}

// ---------------- CSR build ----------------
__global__ void k_zero_deg(int N) {
    int i = blockIdx.x * blockDim.x + threadIdx.x;
    if (i < N) g_deg[i] = 0;
}
__global__ void k_count(const int* __restrict__ ei, int E, int N) {
    int j = blockIdx.x * blockDim.x + threadIdx.x;
    if (j >= E + N) return;
    int d = (j < E) ? ei[E + j] : (j - E);
    atomicAdd(&g_deg[d], 1);
}
__global__ void k_scan1(int N) {
    __shared__ int s[256];
    int t = threadIdx.x, b = blockIdx.x;
    int i0 = b * 1024 + t * 4;
    int sum = 0;
#pragma unroll
    for (int j = 0; j < 4; j++)
        if (i0 + j < N) sum += g_deg[i0 + j];
    s[t] = sum;
    __syncthreads();
#pragma unroll
    for (int off = 128; off; off >>= 1) {
        if (t < off) s[t] += s[t + off];
        __syncthreads();
    }
    if (t == 0) g_bsum[b] = s[0];
}
__global__ void k_scan2(int nb) {
    __shared__ int s[256];
    int t = threadIdx.x;
    int v = (t < nb) ? g_bsum[t] : 0;
    s[t] = v;
    __syncthreads();
#pragma unroll
    for (int off = 1; off < 256; off <<= 1) {
        int u = (t >= off) ? s[t - off] : 0;
        __syncthreads();
        s[t] += u;
        __syncthreads();
    }
    if (t <= nb) g_bpre[t] = (t == 0) ? 0 : s[t - 1];
    if (t == 255) g_bpre[256] = s[255];
}
__global__ void k_scan3(int N, int nb) {
    __shared__ int s[256];
    int t = threadIdx.x, b = blockIdx.x;
    int i0 = b * 1024 + t * 4;
    int d[4];
    int sum = 0;
#pragma unroll
    for (int j = 0; j < 4; j++) {
        d[j] = (i0 + j < N) ? g_deg[i0 + j] : 0;
        sum += d[j];
    }
    s[t] = sum;
    __syncthreads();
#pragma unroll
    for (int off = 1; off < 256; off <<= 1) {
        int u = (t >= off) ? s[t - off] : 0;
        __syncthreads();
        s[t] += u;
        __syncthreads();
    }
    int run = g_bpre[b] + s[t] - sum;
#pragma unroll
    for (int j = 0; j < 4; j++) {
        if (i0 + j < N) {
            g_rowptr[i0 + j] = run;
            g_cursor[i0 + j] = run;
        }
        run += d[j];
    }
    if (b == 0 && t == 0) g_rowptr[N] = g_bpre[nb];
}
__global__ void k_scatter(const int* __restrict__ ei, int E, int N) {
    int j = blockIdx.x * blockDim.x + threadIdx.x;
    if (j >= E + N) return;
    int sIdx, d;
    if (j < E) { sIdx = ei[j]; d = ei[E + j]; }
    else       { sIdx = j - E; d = j - E; }
    int pos = atomicAdd(&g_cursor[d], 1);
    g_srcs[pos] = sIdx;
}

// ---------------- bf16x3 tensor-core GEMM (mma.sync) + fused alpha dots ----------------
// R7 config: 512 threads, 16 warps in 4(M) x 4(N); warp tile 32x32.
#define AS_STRIDE 136
#define TILE_B (128 * AS_STRIDE * 2)
#define OFF_AH 0
#define OFF_AL (TILE_B)
#define OFF_BH (2 * TILE_B)
#define OFF_BL (3 * TILE_B)
#define OFF_SAS (4 * TILE_B)
#define OFF_SAD (OFF_SAS + 512)
#define OFF_SUA (OFF_SAD + 512)
#define OFF_SUD (OFF_SUA + 512)
#define GEMM_SMEM (OFF_SUD + 512)

__global__ void __launch_bounds__(512)
k_gemm_mma(int layer, const float* __restrict__ av_s, const float* __restrict__ av_d, int Nn) {
    extern __shared__ char smem[];
    const uint32_t sb = smem_u32(smem);
    const int tid = threadIdx.x, lane = tid & 31, wid = tid >> 5;
    const int row0 = blockIdx.x * 128;

    float* s_as = (float*)(smem + OFF_SAS);
    float* s_ad = (float*)(smem + OFF_SAD);
    float* s_ua = (float*)(smem + OFF_SUA);
    float* s_ud = (float*)(smem + OFF_SUD);
    if (tid < 128) {
        s_as[tid] = av_s[tid];
        s_ad[tid] = av_d[tid];
        s_ua[tid] = 0.f;
        s_ud[tid] = 0.f;
    }

    {   // stage: pure copies (pre-split bf16 in global); 4 threads per 128-elem row
        int r = tid >> 2, seg = (tid & 3) * 32;
        int gr = min(row0 + r, Nn - 1);
        const uint4* sAh = (const uint4*)&g_xh[(size_t)gr * 128 + seg];
        const uint4* sAl = (const uint4*)&g_xl[(size_t)gr * 128 + seg];
        const uint4* sBh = (const uint4*)&g_wh[layer][r * 128 + seg];
        const uint4* sBl = (const uint4*)&g_wl[layer][r * 128 + seg];
        uint4* dAh = (uint4*)((__nv_bfloat16*)(smem + OFF_AH) + r * AS_STRIDE + seg);
        uint4* dAl = (uint4*)((__nv_bfloat16*)(smem + OFF_AL) + r * AS_STRIDE + seg);
        uint4* dBh = (uint4*)((__nv_bfloat16*)(smem + OFF_BH) + r * AS_STRIDE + seg);
        uint4* dBl = (uint4*)((__nv_bfloat16*)(smem + OFF_BL) + r * AS_STRIDE + seg);
#pragma unroll
        for (int j = 0; j < 4; j++) {
            dAh[j] = sAh[j];
            dAl[j] = sAl[j];
            dBh[j] = sBh[j];
            dBl[j] = sBl[j];
        }
    }
    __syncthreads();

    const int wm = wid & 3, wn = wid >> 2;
    const int wrow = wm * 32, wcol = wn * 32;
    float acc[2][4][4];
#pragma unroll
    for (int i = 0; i < 2; i++)
#pragma unroll
        for (int j = 0; j < 4; j++)
#pragma unroll
            for (int q = 0; q < 4; q++) acc[i][j][q] = 0.f;

    const int lr = lane & 15, lc = lane >> 4;
#pragma unroll
    for (int pass = 0; pass < 3; pass++) {
        uint32_t aoff = sb + ((pass == 1) ? OFF_AL : OFF_AH);
        uint32_t boff = sb + ((pass == 2) ? OFF_BL : OFF_BH);
#pragma unroll
        for (int ks = 0; ks < 8; ks++) {
            int k0 = ks * 16;
            uint32_t a[2][4], b[2][4];
#pragma unroll
            for (int mt = 0; mt < 2; mt++)
                ldsm_x4(a[mt], aoff + ((wrow + mt * 16 + lr) * AS_STRIDE + lc * 8 + k0) * 2);
#pragma unroll
            for (int ng = 0; ng < 2; ng++)
                ldsm_x4_t(b[ng], boff + ((k0 + lr) * AS_STRIDE + wcol + ng * 16 + lc * 8) * 2);
#pragma unroll
            for (int mt = 0; mt < 2; mt++)
#pragma unroll
                for (int nt = 0; nt < 4; nt++)
                    mma_bf16(acc[mt][nt], a[mt], &b[nt >> 1][(nt & 1) * 2]);
        }
    }

    float pa[4] = {0.f, 0.f, 0.f, 0.f}, pd[4] = {0.f, 0.f, 0.f, 0.f};
#pragma unroll
    for (int mt = 0; mt < 2; mt++) {
#pragma unroll
        for (int half = 0; half < 2; half++) {
            int rl = wrow + mt * 16 + half * 8 + (lane >> 2);
            int gr = row0 + rl;
            bool ok = gr < Nn;
#pragma unroll
            for (int nt = 0; nt < 4; nt++) {
                int cl = wcol + nt * 8 + (lane & 3) * 2;
                float v0 = acc[mt][nt][half * 2 + 0];
                float v1 = acc[mt][nt][half * 2 + 1];
                if (ok) *(__half2*)&g_h[(size_t)gr * 128 + cl] = __floats2half2_rn(v0, v1);
                pa[mt * 2 + half] += v0 * s_as[cl] + v1 * s_as[cl + 1];
                pd[mt * 2 + half] += v0 * s_ad[cl] + v1 * s_ad[cl + 1];
            }
        }
    }
#pragma unroll
    for (int i = 0; i < 4; i++) {
        int rl = wrow + (i >> 1) * 16 + (i & 1) * 8 + (lane >> 2);
        atomicAdd(&s_ua[rl], pa[i]);
        atomicAdd(&s_ud[rl], pd[i]);
    }
    __syncthreads();
    if (tid < 128 && row0 + tid < Nn) {
        g_asrc[row0 + tid] = s_ua[tid];
        g_adst[row0 + tid] = s_ud[tid];
    }
}

// ---------------- two-pass softmax aggregation, one warp per dst ----------------
__global__ void k_aggregate(const float* __restrict__ bias, float* __restrict__ outp,
                            int N, int write_final) {
    int warp = (blockIdx.x * blockDim.x + threadIdx.x) >> 5;
    int lane = threadIdx.x & 31;
    if (warp >= N) return;

    int beg = g_rowptr[warp];
    int end = g_rowptr[warp + 1];
    float ad = g_adst[warp];

    // pass 1: segment max
    float m = -1e30f;
    for (int e = beg + lane; e < end; e += 32) {
        int s = __ldg(&g_srcs[e]);
        float v = __ldg(&g_asrc[s]) + ad;
        v = v > 0.f ? v : 0.2f * v;
        m = fmaxf(m, v);
    }
#pragma unroll
    for (int off = 16; off; off >>= 1)
        m = fmaxf(m, __shfl_xor_sync(0xffffffffu, m, off));

    // pass 2: unnormalized weighted sum (h rows stored fp16, 8B per lane)
    float4 acc = make_float4(0.f, 0.f, 0.f, 0.f);
    float denom = 0.f;
    for (int base = beg; base < end; base += 32) {
        int e = base + lane;
        float w = 0.f;
        int s = 0;
        if (e < end) {
            s = __ldg(&g_srcs[e]);
            float v = __ldg(&g_asrc[s]) + ad;
            v = v > 0.f ? v : 0.2f * v;
            w = __expf(v - m);
        }
        denom += w;
        int cnt = min(32, end - base);
        for (int i = 0; i < cnt; i++) {
            float wi = __shfl_sync(0xffffffffu, w, i);
            int   si = __shfl_sync(0xffffffffu, s, i);
            uint2 raw = __ldg((const uint2*)&g_h[(size_t)si * 128 + lane * 4]);
            __half2 h01 = *reinterpret_cast<__half2*>(&raw.x);
            __half2 h23 = *reinterpret_cast<__half2*>(&raw.y);
            float2 f01 = __half22float2(h01);
            float2 f23 = __half22float2(h23);
            acc.x += wi * f01.x; acc.y += wi * f01.y;
            acc.z += wi * f23.x; acc.w += wi * f23.y;
        }
    }
#pragma unroll
    for (int off = 16; off; off >>= 1)
        denom += __shfl_xor_sync(0xffffffffu, denom, off);

    float inv = 1.f / denom;
    float4 bv = *(const float4*)&bias[lane * 4];
    float4 r;
    r.x = acc.x * inv + bv.x;
    r.y = acc.y * inv + bv.y;
    r.z = acc.z * inv + bv.z;
    r.w = acc.w * inv + bv.w;
    if (write_final) {
        *(float4*)&outp[(size_t)warp * 128 + lane * 4] = r;
    } else {
        r.x = r.x > 0.f ? r.x : expm1f(r.x);
        r.y = r.y > 0.f ? r.y : expm1f(r.y);
        r.z = r.z > 0.f ? r.z : expm1f(r.z);
        r.w = r.w > 0.f ? r.w : expm1f(r.w);
        size_t idx = (size_t)warp * 128 + lane * 4;
        split4_store(r, &g_xh[idx], &g_xl[idx]);
    }
}

// ---------------- launch ----------------
extern "C" void kernel_launch(void* const* d_in, const int* in_sizes, int n_in,
                              void* d_out, int out_size) {
    const float* x  = (const float*)d_in[0];
    const int*   ei = (const int*)d_in[1];
    int N  = in_sizes[0] / F;
    int E  = in_sizes[1] / 2;
    int ET = E + N;
    int nb = (N + 1023) / 1024;

    static int smem_set = 0;
    if (!smem_set) {
        cudaFuncSetAttribute(k_gemm_mma, cudaFuncAttributeMaxDynamicSharedMemorySize, GEMM_SMEM);
        smem_set = 1;
    }

    int warp_blocks = (N * 32 + 255) / 256;
    int gemm_blocks = (N + 127) / 128;

    // launch #4 = k_gemm_mma (ncu captures the 4th launch)
    k_split_x<<<(N * 32 + 255) / 256, 256>>>(x, N * 32);
    k_prepW_all<<<48, 256>>>((const float*)d_in[2], (const float*)d_in[6], (const float*)d_in[10]);
    k_zero_deg<<<(N + 255) / 256, 256>>>(N);
    k_gemm_mma<<<gemm_blocks, 512, GEMM_SMEM>>>(0, (const float*)d_in[3], (const float*)d_in[4], N);
    k_count<<<(ET + 255) / 256, 256>>>(ei, E, N);
    k_scan1<<<nb, 256>>>(N);
    k_scan2<<<1, 256>>>(nb);
    k_scan3<<<nb, 256>>>(N, nb);
    k_scatter<<<(ET + 255) / 256, 256>>>(ei, E, N);

    for (int l = 0; l < 3; l++) {
        const float* as = (const float*)d_in[3 + 4 * l];
        const float* ad = (const float*)d_in[4 + 4 * l];
        const float* b  = (const float*)d_in[5 + 4 * l];
        if (l > 0)
            k_gemm_mma<<<gemm_blocks, 512, GEMM_SMEM>>>(l, as, ad, N);
        k_aggregate<<<warp_blocks, 256>>>(b, l == 2 ? (float*)d_out : nullptr, N, l == 2 ? 1 : 0);
    }
}